// round 14
// baseline (speedup 1.0000x reference)
#include <cuda_runtime.h>
#include <cuda_fp16.h>
#include <math.h>
#include <stdint.h>

#define NN 8192
#define INF_ 128
#define OUTF 64

typedef unsigned int u32;

#define JSPLIT 4
#define JPC (NN / JSPLIT)        // 2048 j per CTA
#define RB2 128                  // rows per k2 CTA
#define NK16 (JPC / 16)          // 128 k16-steps
#define K2T 256

// ---------------- scratch (__device__ globals; no allocation) ------------------
__device__ __half g_WhH[72 * NN];           // [n][j] fp16; 0..63 = WhT, 64 = ones, 65..71 = 0
__device__ float g_E1[NN], g_F1[NN];        // exp(f1), exp(0.2 f1)   (unscaled)
__device__ float g_E2[NN], g_F2[NN];        // exp(f2), exp(0.2 f2)
__device__ int   g_ME2i, g_MF2i;            // global max of E2 / F2 (float bits, >0)
__device__ float g_part[JSPLIT * NN * OUTF];// numerator partials
__device__ float g_denp[JSPLIT * NN];       // denominator partials

// ---------------- helpers -------------------------------------------------------
__device__ __forceinline__ u32 packh2(float hi, float lo) {
    u32 d; asm("cvt.rn.f16x2.f32 %0, %1, %2;" : "=r"(d) : "f"(hi), "f"(lo));
    return d;
}
__device__ __forceinline__ u32 pairmask2(u32 ax, u32 ay) {   // adj in {0,1}
    return ((u32)(-(int)ax) & 0xFFFFu) | ((u32)(-(int)ay) << 16);
}
__device__ __forceinline__ u32 smem_u32(const void* p) {
    u32 a;
    asm("{ .reg .u64 t; cvta.to.shared.u64 t, %1; cvt.u32.u64 %0, t; }" : "=r"(a) : "l"(p));
    return a;
}
__device__ __forceinline__ void cpa16(u32 dst, const void* src) {
    asm volatile("cp.async.cg.shared.global [%0], [%1], 16;" :: "r"(dst), "l"(src));
}
__device__ __forceinline__ void cpa_commit() {
    asm volatile("cp.async.commit_group;" ::: "memory");
}
#define CPA_WAIT(n) asm volatile("cp.async.wait_group %0;" :: "n"(n) : "memory")

// m16n8k16 fp16 MMA (row.col), f32 accum.
__device__ __forceinline__ void mma_f16(float* d, u32 a0, u32 a1, u32 a2, u32 a3,
                                        u32 b0, u32 b1) {
    asm volatile(
        "mma.sync.aligned.m16n8k16.row.col.f32.f16.f16.f32 "
        "{%0,%1,%2,%3}, {%4,%5,%6,%7}, {%8,%9}, {%0,%1,%2,%3};"
        : "+f"(d[0]), "+f"(d[1]), "+f"(d[2]), "+f"(d[3])
        : "r"(a0), "r"(a1), "r"(a2), "r"(a3), "r"(b0), "r"(b1));
}

// ---------------- kernel 1: Wh = h @ W -> g_WhH (fp16), E/F factors, maxes -----
// 64 rows/CTA, 256 threads, 4x4 register tile (measured-best shape, 10.4 us).
#define K1_ROWS 64
#define K1T 256
#define SH 132                          // h row stride in floats
#define K1_SMEM ((INF_ * OUTF + K1_ROWS * SH) * 4)   // 66560 bytes

__global__ void __launch_bounds__(K1T)
k1_proj(const float* __restrict__ h, const float* __restrict__ W,
        const float* __restrict__ a) {
    extern __shared__ float smk1[];
    float* sW = smk1;                   // [128][64]
    float* sh = smk1 + INF_ * OUTF;     // [64][SH]
    __shared__ float redA[16], redB[16];

    const int tid  = threadIdx.x;
    const int row0 = blockIdx.x * K1_ROWS;

    #pragma unroll
    for (int q = 0; q < 8; q++)         // W: 2048 float4
        ((float4*)sW)[tid + q * K1T] = ((const float4*)W)[tid + q * K1T];
    #pragma unroll
    for (int q = 0; q < 8; q++) {       // h: 2048 float4
        int slot = tid + q * K1T;
        int r = slot >> 5, cq = slot & 31;
        *(float4*)&sh[r * SH + cq * 4] =
            *(const float4*)&h[(size_t)(row0 + r) * INF_ + cq * 4];
    }
    __syncthreads();

    const int fg = tid & 15;            // 16 col groups * 4
    const int rg = tid >> 4;            // 16 row groups * 4
    const int f0 = fg * 4;
    const int r0 = rg * 4;

    float acc[4][4] = {};
    #pragma unroll 16
    for (int k = 0; k < INF_; k++) {
        float4 b = *(const float4*)&sW[k * OUTF + f0];
        #pragma unroll
        for (int rr = 0; rr < 4; rr++) {
            float x = sh[(r0 + rr) * SH + k];
            acc[rr][0] += x * b.x; acc[rr][1] += x * b.y;
            acc[rr][2] += x * b.z; acc[rr][3] += x * b.w;
        }
    }

    // store Wh as fp16, transposed: g_WhH[f][row], 4 rows packed per store
    #pragma unroll
    for (int cc = 0; cc < 4; cc++) {
        __half2 lo = __floats2half2_rn(acc[0][cc], acc[1][cc]);
        __half2 hi = __floats2half2_rn(acc[2][cc], acc[3][cc]);
        uint2 v = make_uint2(*(u32*)&lo, *(u32*)&hi);
        *(uint2*)&g_WhH[(size_t)(f0 + cc) * NN + row0 + r0] = v;
    }

    float a1[4], a2[4];
    #pragma unroll
    for (int c = 0; c < 4; c++) { a1[c] = a[f0 + c]; a2[c] = a[OUTF + f0 + c]; }

    float locE2 = 0.f, locF2 = 0.f;
    #pragma unroll
    for (int rr = 0; rr < 4; rr++) {
        float p1 = acc[rr][0]*a1[0] + acc[rr][1]*a1[1] + acc[rr][2]*a1[2] + acc[rr][3]*a1[3];
        float p2 = acc[rr][0]*a2[0] + acc[rr][1]*a2[1] + acc[rr][2]*a2[2] + acc[rr][3]*a2[3];
        #pragma unroll
        for (int off = 8; off >= 1; off >>= 1) {
            p1 += __shfl_down_sync(0xffffffffu, p1, off, 16);
            p2 += __shfl_down_sync(0xffffffffu, p2, off, 16);
        }
        if (fg == 0) {
            int row = row0 + r0 + rr;
            float e1 = expf(p1), fl1 = expf(0.2f * p1);
            float e2 = expf(p2), fl2 = expf(0.2f * p2);
            g_E1[row] = e1;  g_F1[row] = fl1;
            g_E2[row] = e2;  g_F2[row] = fl2;
            locE2 = fmaxf(locE2, e2); locF2 = fmaxf(locF2, fl2);
        }
    }
    if (fg == 0) { redA[rg] = locE2; redB[rg] = locF2; }

    // constant rows 64..71 (ones column for denominator, zero padding)
    for (int i = tid; i < 8 * K1_ROWS; i += K1T) {
        int f = 64 + (i >> 6);
        int r = row0 + (i & 63);
        g_WhH[(size_t)f * NN + r] = (f == 64) ? __float2half(1.0f) : __float2half(0.0f);
    }
    __syncthreads();
    if (tid == 0) {
        float mA = 0.f, mB = 0.f;
        #pragma unroll
        for (int i = 0; i < 16; i++) { mA = fmaxf(mA, redA[i]); mB = fmaxf(mB, redB[i]); }
        atomicMax(&g_ME2i, __float_as_int(mA));
        atomicMax(&g_MF2i, __float_as_int(mB));
    }
}

// ---------------- kernel 2: fused mask+weight-gen + fp16 tensor aggregate ------
// Per CTA: 128 rows x 2048 j. 8 warps, each m16 x n72 (n-col 64 = ones/denominator).
// j-permutation: lane (g,c) owns j = t*16 + 4c..4c+3. Single-sync double-buffered
// cp.async B pipeline. 3 CTAs/SM (24 warps), adj register-prefetch depth 2
// (latency hidden by warp count instead of per-warp depth).
#define SBH 80                            // halves stride per B n-row (160 B)
#define SB_BYTES (72 * SBH * 2)           // 11520
#define SMEM_K2 (JPC * 8 + 2 * SB_BYTES)  // sE+sF (16 KB) + 2 B bufs = 39424 B

__global__ void __launch_bounds__(K2T, 3)
k2_gat(const int* __restrict__ adj) {
    extern __shared__ char smraw[];
    float* sE = (float*)smraw;                         // [JPC] E2 slice
    float* sF = (float*)(smraw + JPC * 4);             // [JPC] F2 slice
    __half* sB0 = (__half*)(smraw + JPC * 8);
    __half* sB1 = (__half*)(smraw + JPC * 8 + SB_BYTES);
    const u32 sE_a  = smem_u32(sE);
    const u32 sF_a  = smem_u32(sF);
    const u32 sB0_a = smem_u32(sB0);
    const u32 sB1_a = smem_u32(sB1);

    const int tid  = threadIdx.x;
    const int wid  = tid >> 5;
    const int g    = (tid & 31) >> 2;
    const int c    = tid & 3;
    const int rb   = blockIdx.x & 63;
    const int js   = blockIdx.x >> 6;
    const int row0 = rb * RB2;
    const int jbase = js * JPC;
    const int r0w  = row0 + wid * 16;

    // ---- group 0: sE, sF, B chunk 0 (cp.async) ----
    #pragma unroll
    for (int q = 0; q < 2; q++) {
        int i = tid + q * K2T;            // 512 float4 each
        cpa16(sE_a + i * 16, &g_E2[jbase + 4 * i]);
        cpa16(sF_a + i * 16, &g_F2[jbase + 4 * i]);
    }
    #pragma unroll
    for (int q = 0; q < 3; q++) {
        int slot = tid + q * K2T;
        if (slot < 576) {                 // 72 n-rows x 8 x 16B
            int n = slot >> 3, p = slot & 7;
            cpa16(sB0_a + n * 160 + p * 16, &g_WhH[(size_t)n * NN + jbase + p * 8]);
        }
    }
    cpa_commit();

    // ---- row factors, rescaled so weights <= 1 (softmax-invariant) ----
    const float ME2 = __int_as_float(g_ME2i);
    const float MF2 = __int_as_float(g_MF2i);
    float e1r[2], f1r[2];
    #pragma unroll
    for (int rr = 0; rr < 2; rr++) {
        int row = r0w + rr * 8 + g;
        float e1 = g_E1[row], f1 = g_F1[row];
        float inv = 1.0f / fmaxf(e1 * ME2, f1 * MF2);
        e1r[rr] = e1 * inv;
        f1r[rr] = f1 * inv;
    }
    // ---- adj pointers + depth-2 register prefetch (uint4 per lane) ----
    const int* ap[2];
    #pragma unroll
    for (int rr = 0; rr < 2; rr++)
        ap[rr] = adj + (size_t)(r0w + rr * 8 + g) * NN + jbase + 4 * c;
    uint4 av[2][2];
    #pragma unroll
    for (int s = 0; s < 2; s++)
        #pragma unroll
        for (int rr = 0; rr < 2; rr++)
            av[s][rr] = *(const uint4*)(ap[rr] + s * 16);

    float acc[9][4];
    #pragma unroll
    for (int nt = 0; nt < 9; nt++)
        #pragma unroll
        for (int q = 0; q < 4; q++) acc[nt][q] = 0.f;

    for (int ch = 0; ch < 32; ch++) {
        const __half* sb = (ch & 1) ? sB1 : sB0;
        CPA_WAIT(0);                      // buf ch ready (incl. sE/sF at ch=0)
        __syncthreads();
        if (ch + 1 < 32) {                // stage next chunk AFTER the sync:
            const u32 dsta = (ch & 1) ? sB0_a : sB1_a;   // readers of that buf
            #pragma unroll                                // finished pre-sync
            for (int q = 0; q < 3; q++) {
                int slot = tid + q * K2T;
                if (slot < 576) {
                    int n = slot >> 3, p = slot & 7;
                    cpa16(dsta + n * 160 + p * 16,
                          &g_WhH[(size_t)n * NN + jbase + (ch + 1) * 64 + p * 8]);
                }
            }
            cpa_commit();
        }

        #pragma unroll
        for (int k16 = 0; k16 < 4; k16++) {
            const int t  = ch * 4 + k16;
            const int sl = t & 1;
            uint4 a0v[2];
            #pragma unroll
            for (int rr = 0; rr < 2; rr++) a0v[rr] = av[sl][rr];
            if (t + 2 < NK16) {
                #pragma unroll
                for (int rr = 0; rr < 2; rr++)
                    av[sl][rr] = *(const uint4*)(ap[rr] + (t + 2) * 16);
            }
            float4 Eq = *(const float4*)&sE[t * 16 + 4 * c];   // j = t*16+4c..4c+3
            float4 Fq = *(const float4*)&sF[t * 16 + 4 * c];
            u32 A0[2], A2[2];
            #pragma unroll
            for (int rr = 0; rr < 2; rr++) {
                float w0 = fmaxf(e1r[rr] * Eq.x, f1r[rr] * Fq.x);
                float w1 = fmaxf(e1r[rr] * Eq.y, f1r[rr] * Fq.y);
                float w2 = fmaxf(e1r[rr] * Eq.z, f1r[rr] * Fq.z);
                float w3 = fmaxf(e1r[rr] * Eq.w, f1r[rr] * Fq.w);
                A0[rr] = packh2(w1, w0) & pairmask2(a0v[rr].x, a0v[rr].y);
                A2[rr] = packh2(w3, w2) & pairmask2(a0v[rr].z, a0v[rr].w);
            }
            #pragma unroll
            for (int nt = 0; nt < 9; nt++) {
                uint2 b = *(const uint2*)&sb[(nt * 8 + g) * SBH + k16 * 16 + 4 * c];
                mma_f16(acc[nt], A0[0], A0[1], A2[0], A2[1], b.x, b.y);
            }
        }
    }

    // ---- epilogue: write partials (row scaling cancels in num/den) ----
    {
        int ra = r0w + g;
        int rc = r0w + 8 + g;
        #pragma unroll
        for (int nt = 0; nt < 8; nt++) {
            int col = nt * 8 + 2 * c;
            *(float2*)&g_part[((size_t)js * NN + ra) * OUTF + col] =
                make_float2(acc[nt][0], acc[nt][1]);
            *(float2*)&g_part[((size_t)js * NN + rc) * OUTF + col] =
                make_float2(acc[nt][2], acc[nt][3]);
        }
        if (c == 0) {                    // n-col 64 (ones) = denominator
            g_denp[js * NN + ra] = acc[8][0];
            g_denp[js * NN + rc] = acc[8][2];
        }
    }
}

// ---------------- kernel 3: reduce partials, normalize, elu (vectorized) -------
__global__ void __launch_bounds__(256)
k3_final(float* __restrict__ out) {
    int q   = blockIdx.x * 256 + threadIdx.x;   // float4 index
    int idx = q * 4;
    int row = idx >> 6;
    float4 num = make_float4(0.f, 0.f, 0.f, 0.f);
    float den = 0.f;
    #pragma unroll
    for (int s = 0; s < JSPLIT; s++) {
        float4 p = *(const float4*)&g_part[(size_t)s * NN * OUTF + idx];
        num.x += p.x; num.y += p.y; num.z += p.z; num.w += p.w;
        den += g_denp[s * NN + row];
    }
    float inv = 1.f / den;
    float v0 = num.x * inv, v1 = num.y * inv, v2 = num.z * inv, v3 = num.w * inv;
    v0 = (v0 > 0.f) ? v0 : expm1f(v0);
    v1 = (v1 > 0.f) ? v1 : expm1f(v1);
    v2 = (v2 > 0.f) ? v2 : expm1f(v2);
    v3 = (v3 > 0.f) ? v3 : expm1f(v3);
    *(float4*)&out[idx] = make_float4(v0, v1, v2, v3);
}

// ---------------- launcher -----------------------------------------------------
extern "C" void kernel_launch(void* const* d_in, const int* in_sizes, int n_in,
                              void* d_out, int out_size) {
    const float* h = nullptr; const int* adj = nullptr;
    const float* W = nullptr; const float* a = nullptr;
    for (int i = 0; i < n_in; i++) {
        switch (in_sizes[i]) {
            case 1048576:  h   = (const float*)d_in[i]; break;
            case 67108864: adj = (const int*)  d_in[i]; break;
            case 8192:     W   = (const float*)d_in[i]; break;
            case 128:      a   = (const float*)d_in[i]; break;
            default: break;
        }
    }
    float* out = (float*)d_out;

    cudaFuncSetAttribute(k1_proj, cudaFuncAttributeMaxDynamicSharedMemorySize, K1_SMEM);

    k1_proj<<<NN / K1_ROWS, K1T, K1_SMEM>>>(h, W, a);
    k2_gat<<<64 * JSPLIT, K2T, SMEM_K2>>>(adj);
    k3_final<<<(NN * OUTF) / 1024, 256>>>(out);
    (void)out_size;
}

// round 15
// speedup vs baseline: 1.8815x; 1.8815x over previous
#include <cuda_runtime.h>
#include <cuda_fp16.h>
#include <math.h>
#include <stdint.h>

#define NN 8192
#define INF_ 128
#define OUTF 64

typedef unsigned int u32;

#define JSPLIT 4
#define JPC (NN / JSPLIT)        // 2048 j per CTA
#define RB2 128                  // rows per k2 CTA
#define NK16 (JPC / 16)          // 128 k16-steps
#define K2T 256
#define CHJ 128                  // j per B chunk (was 64) -> 16 chunks
#define NCH (JPC / CHJ)          // 16

// ---------------- scratch (__device__ globals; no allocation) ------------------
__device__ __half g_WhH[72 * NN];           // [n][j] fp16; 0..63 = WhT, 64 = ones, 65..71 = 0
__device__ float g_E1[NN], g_F1[NN];        // exp(f1), exp(0.2 f1)   (unscaled)
__device__ float g_E2[NN], g_F2[NN];        // exp(f2), exp(0.2 f2)
__device__ int   g_ME2i, g_MF2i;            // global max of E2 / F2 (float bits, >0)
__device__ float g_part[JSPLIT * NN * OUTF];// numerator partials
__device__ float g_denp[JSPLIT * NN];       // denominator partials

// ---------------- helpers -------------------------------------------------------
__device__ __forceinline__ u32 packh2(float hi, float lo) {
    u32 d; asm("cvt.rn.f16x2.f32 %0, %1, %2;" : "=r"(d) : "f"(hi), "f"(lo));
    return d;
}
__device__ __forceinline__ u32 pairmask2(u32 ax, u32 ay) {   // adj in {0,1}
    return ((u32)(-(int)ax) & 0xFFFFu) | ((u32)(-(int)ay) << 16);
}
__device__ __forceinline__ u32 smem_u32(const void* p) {
    u32 a;
    asm("{ .reg .u64 t; cvta.to.shared.u64 t, %1; cvt.u32.u64 %0, t; }" : "=r"(a) : "l"(p));
    return a;
}
__device__ __forceinline__ void cpa16(u32 dst, const void* src) {
    asm volatile("cp.async.cg.shared.global [%0], [%1], 16;" :: "r"(dst), "l"(src));
}
__device__ __forceinline__ void cpa_commit() {
    asm volatile("cp.async.commit_group;" ::: "memory");
}
#define CPA_WAIT(n) asm volatile("cp.async.wait_group %0;" :: "n"(n) : "memory")

// m16n8k16 fp16 MMA (row.col), f32 accum.
__device__ __forceinline__ void mma_f16(float* d, u32 a0, u32 a1, u32 a2, u32 a3,
                                        u32 b0, u32 b1) {
    asm volatile(
        "mma.sync.aligned.m16n8k16.row.col.f32.f16.f16.f32 "
        "{%0,%1,%2,%3}, {%4,%5,%6,%7}, {%8,%9}, {%0,%1,%2,%3};"
        : "+f"(d[0]), "+f"(d[1]), "+f"(d[2]), "+f"(d[3])
        : "r"(a0), "r"(a1), "r"(a2), "r"(a3), "r"(b0), "r"(b1));
}

// ---------------- kernel 1: Wh = h @ W -> g_WhH (fp16), E/F factors, maxes -----
// 64 rows/CTA, 256 threads, 4x4 register tile (measured-best shape, 10.4 us).
#define K1_ROWS 64
#define K1T 256
#define SH 132                          // h row stride in floats
#define K1_SMEM ((INF_ * OUTF + K1_ROWS * SH) * 4)   // 66560 bytes

__global__ void __launch_bounds__(K1T)
k1_proj(const float* __restrict__ h, const float* __restrict__ W,
        const float* __restrict__ a) {
    extern __shared__ float smk1[];
    float* sW = smk1;                   // [128][64]
    float* sh = smk1 + INF_ * OUTF;     // [64][SH]
    __shared__ float redA[16], redB[16];

    const int tid  = threadIdx.x;
    const int row0 = blockIdx.x * K1_ROWS;

    #pragma unroll
    for (int q = 0; q < 8; q++)         // W: 2048 float4
        ((float4*)sW)[tid + q * K1T] = ((const float4*)W)[tid + q * K1T];
    #pragma unroll
    for (int q = 0; q < 8; q++) {       // h: 2048 float4
        int slot = tid + q * K1T;
        int r = slot >> 5, cq = slot & 31;
        *(float4*)&sh[r * SH + cq * 4] =
            *(const float4*)&h[(size_t)(row0 + r) * INF_ + cq * 4];
    }
    __syncthreads();

    const int fg = tid & 15;            // 16 col groups * 4
    const int rg = tid >> 4;            // 16 row groups * 4
    const int f0 = fg * 4;
    const int r0 = rg * 4;

    float acc[4][4] = {};
    #pragma unroll 16
    for (int k = 0; k < INF_; k++) {
        float4 b = *(const float4*)&sW[k * OUTF + f0];
        #pragma unroll
        for (int rr = 0; rr < 4; rr++) {
            float x = sh[(r0 + rr) * SH + k];
            acc[rr][0] += x * b.x; acc[rr][1] += x * b.y;
            acc[rr][2] += x * b.z; acc[rr][3] += x * b.w;
        }
    }

    // store Wh as fp16, transposed: g_WhH[f][row], 4 rows packed per store
    #pragma unroll
    for (int cc = 0; cc < 4; cc++) {
        __half2 lo = __floats2half2_rn(acc[0][cc], acc[1][cc]);
        __half2 hi = __floats2half2_rn(acc[2][cc], acc[3][cc]);
        uint2 v = make_uint2(*(u32*)&lo, *(u32*)&hi);
        *(uint2*)&g_WhH[(size_t)(f0 + cc) * NN + row0 + r0] = v;
    }

    float a1[4], a2[4];
    #pragma unroll
    for (int c = 0; c < 4; c++) { a1[c] = a[f0 + c]; a2[c] = a[OUTF + f0 + c]; }

    float locE2 = 0.f, locF2 = 0.f;
    #pragma unroll
    for (int rr = 0; rr < 4; rr++) {
        float p1 = acc[rr][0]*a1[0] + acc[rr][1]*a1[1] + acc[rr][2]*a1[2] + acc[rr][3]*a1[3];
        float p2 = acc[rr][0]*a2[0] + acc[rr][1]*a2[1] + acc[rr][2]*a2[2] + acc[rr][3]*a2[3];
        #pragma unroll
        for (int off = 8; off >= 1; off >>= 1) {
            p1 += __shfl_down_sync(0xffffffffu, p1, off, 16);
            p2 += __shfl_down_sync(0xffffffffu, p2, off, 16);
        }
        if (fg == 0) {
            int row = row0 + r0 + rr;
            float e1 = expf(p1), fl1 = expf(0.2f * p1);
            float e2 = expf(p2), fl2 = expf(0.2f * p2);
            g_E1[row] = e1;  g_F1[row] = fl1;
            g_E2[row] = e2;  g_F2[row] = fl2;
            locE2 = fmaxf(locE2, e2); locF2 = fmaxf(locF2, fl2);
        }
    }
    if (fg == 0) { redA[rg] = locE2; redB[rg] = locF2; }

    // constant rows 64..71 (ones column for denominator, zero padding)
    for (int i = tid; i < 8 * K1_ROWS; i += K1T) {
        int f = 64 + (i >> 6);
        int r = row0 + (i & 63);
        g_WhH[(size_t)f * NN + r] = (f == 64) ? __float2half(1.0f) : __float2half(0.0f);
    }
    __syncthreads();
    if (tid == 0) {
        float mA = 0.f, mB = 0.f;
        #pragma unroll
        for (int i = 0; i < 16; i++) { mA = fmaxf(mA, redA[i]); mB = fmaxf(mB, redB[i]); }
        atomicMax(&g_ME2i, __float_as_int(mA));
        atomicMax(&g_MF2i, __float_as_int(mB));
    }
}

// ---------------- kernel 2: fused mask+weight-gen + fp16 tensor aggregate ------
// (R12-measured-best form, with 128-j B chunks -> 16 barriers instead of 32.)
// Per CTA: 128 rows x 2048 j. 8 warps, each m16 x n72 (n-col 64 = ones/denominator).
// j-permutation: lane (g,c) owns j = t*16 + 4c..4c+3. Single-sync double-buffered
// cp.async B pipeline; adj via depth-4 register prefetch of LDG.128. 2 CTAs/SM.
#define SBH 144                           // halves stride per B n-row (288 B; mod128=32,
                                          // same bank pattern as the 160 B baseline)
#define SB_BYTES (72 * SBH * 2)           // 20736
#define SMEM_K2 (JPC * 8 + 2 * SB_BYTES)  // sE+sF (16 KB) + 2 B bufs = 57856 B

__global__ void __launch_bounds__(K2T, 2)
k2_gat(const int* __restrict__ adj) {
    extern __shared__ char smraw[];
    float* sE = (float*)smraw;                         // [JPC] E2 slice
    float* sF = (float*)(smraw + JPC * 4);             // [JPC] F2 slice
    __half* sB0 = (__half*)(smraw + JPC * 8);
    __half* sB1 = (__half*)(smraw + JPC * 8 + SB_BYTES);
    const u32 sE_a  = smem_u32(sE);
    const u32 sF_a  = smem_u32(sF);
    const u32 sB0_a = smem_u32(sB0);
    const u32 sB1_a = smem_u32(sB1);

    const int tid  = threadIdx.x;
    const int wid  = tid >> 5;
    const int g    = (tid & 31) >> 2;
    const int c    = tid & 3;
    const int rb   = blockIdx.x & 63;
    const int js   = blockIdx.x >> 6;
    const int row0 = rb * RB2;
    const int jbase = js * JPC;
    const int r0w  = row0 + wid * 16;

    // ---- group 0: sE, sF, B chunk 0 (cp.async) ----
    #pragma unroll
    for (int q = 0; q < 2; q++) {
        int i = tid + q * K2T;            // 512 float4 each
        cpa16(sE_a + i * 16, &g_E2[jbase + 4 * i]);
        cpa16(sF_a + i * 16, &g_F2[jbase + 4 * i]);
    }
    #pragma unroll
    for (int q = 0; q < 5; q++) {
        int slot = tid + q * K2T;
        if (slot < 1152) {                // 72 n-rows x 16 x 16B
            int n = slot >> 4, p = slot & 15;
            cpa16(sB0_a + n * 288 + p * 16, &g_WhH[(size_t)n * NN + jbase + p * 8]);
        }
    }
    cpa_commit();

    // ---- row factors, rescaled so weights <= 1 (softmax-invariant) ----
    const float ME2 = __int_as_float(g_ME2i);
    const float MF2 = __int_as_float(g_MF2i);
    float e1r[2], f1r[2];
    #pragma unroll
    for (int rr = 0; rr < 2; rr++) {
        int row = r0w + rr * 8 + g;
        float e1 = g_E1[row], f1 = g_F1[row];
        float inv = 1.0f / fmaxf(e1 * ME2, f1 * MF2);
        e1r[rr] = e1 * inv;
        f1r[rr] = f1 * inv;
    }
    // ---- adj pointers + depth-4 register prefetch (uint4 per lane) ----
    const int* ap[2];
    #pragma unroll
    for (int rr = 0; rr < 2; rr++)
        ap[rr] = adj + (size_t)(r0w + rr * 8 + g) * NN + jbase + 4 * c;
    uint4 av[4][2];
    #pragma unroll
    for (int s = 0; s < 4; s++)
        #pragma unroll
        for (int rr = 0; rr < 2; rr++)
            av[s][rr] = *(const uint4*)(ap[rr] + s * 16);

    float acc[9][4];
    #pragma unroll
    for (int nt = 0; nt < 9; nt++)
        #pragma unroll
        for (int q = 0; q < 4; q++) acc[nt][q] = 0.f;

    for (int ch = 0; ch < NCH; ch++) {
        const __half* sb = (ch & 1) ? sB1 : sB0;
        CPA_WAIT(0);                      // buf ch ready (incl. sE/sF at ch=0)
        __syncthreads();
        if (ch + 1 < NCH) {               // stage next chunk AFTER the sync:
            const u32 dsta = (ch & 1) ? sB0_a : sB1_a;   // readers of that buf
            #pragma unroll                                // finished pre-sync
            for (int q = 0; q < 5; q++) {
                int slot = tid + q * K2T;
                if (slot < 1152) {
                    int n = slot >> 4, p = slot & 15;
                    cpa16(dsta + n * 288 + p * 16,
                          &g_WhH[(size_t)n * NN + jbase + (ch + 1) * CHJ + p * 8]);
                }
            }
            cpa_commit();
        }

        #pragma unroll
        for (int k16 = 0; k16 < 8; k16++) {
            const int t  = ch * 8 + k16;
            const int sl = t & 3;
            uint4 a0v[2];
            #pragma unroll
            for (int rr = 0; rr < 2; rr++) a0v[rr] = av[sl][rr];
            if (t + 4 < NK16) {
                #pragma unroll
                for (int rr = 0; rr < 2; rr++)
                    av[sl][rr] = *(const uint4*)(ap[rr] + (t + 4) * 16);
            }
            float4 Eq = *(const float4*)&sE[t * 16 + 4 * c];   // j = t*16+4c..4c+3
            float4 Fq = *(const float4*)&sF[t * 16 + 4 * c];
            u32 A0[2], A2[2];
            #pragma unroll
            for (int rr = 0; rr < 2; rr++) {
                float w0 = fmaxf(e1r[rr] * Eq.x, f1r[rr] * Fq.x);
                float w1 = fmaxf(e1r[rr] * Eq.y, f1r[rr] * Fq.y);
                float w2 = fmaxf(e1r[rr] * Eq.z, f1r[rr] * Fq.z);
                float w3 = fmaxf(e1r[rr] * Eq.w, f1r[rr] * Fq.w);
                A0[rr] = packh2(w1, w0) & pairmask2(a0v[rr].x, a0v[rr].y);
                A2[rr] = packh2(w3, w2) & pairmask2(a0v[rr].z, a0v[rr].w);
            }
            #pragma unroll
            for (int nt = 0; nt < 9; nt++) {
                uint2 b = *(const uint2*)&sb[(nt * 8 + g) * SBH + k16 * 16 + 4 * c];
                mma_f16(acc[nt], A0[0], A0[1], A2[0], A2[1], b.x, b.y);
            }
        }
    }

    // ---- epilogue: write partials (row scaling cancels in num/den) ----
    {
        int ra = r0w + g;
        int rc = r0w + 8 + g;
        #pragma unroll
        for (int nt = 0; nt < 8; nt++) {
            int col = nt * 8 + 2 * c;
            *(float2*)&g_part[((size_t)js * NN + ra) * OUTF + col] =
                make_float2(acc[nt][0], acc[nt][1]);
            *(float2*)&g_part[((size_t)js * NN + rc) * OUTF + col] =
                make_float2(acc[nt][2], acc[nt][3]);
        }
        if (c == 0) {                    // n-col 64 (ones) = denominator
            g_denp[js * NN + ra] = acc[8][0];
            g_denp[js * NN + rc] = acc[8][2];
        }
    }
}

// ---------------- kernel 3: reduce partials, normalize, elu (vectorized) -------
__global__ void __launch_bounds__(256)
k3_final(float* __restrict__ out) {
    int q   = blockIdx.x * 256 + threadIdx.x;   // float4 index
    int idx = q * 4;
    int row = idx >> 6;
    float4 num = make_float4(0.f, 0.f, 0.f, 0.f);
    float den = 0.f;
    #pragma unroll
    for (int s = 0; s < JSPLIT; s++) {
        float4 p = *(const float4*)&g_part[(size_t)s * NN * OUTF + idx];
        num.x += p.x; num.y += p.y; num.z += p.z; num.w += p.w;
        den += g_denp[s * NN + row];
    }
    float inv = 1.f / den;
    float v0 = num.x * inv, v1 = num.y * inv, v2 = num.z * inv, v3 = num.w * inv;
    v0 = (v0 > 0.f) ? v0 : expm1f(v0);
    v1 = (v1 > 0.f) ? v1 : expm1f(v1);
    v2 = (v2 > 0.f) ? v2 : expm1f(v2);
    v3 = (v3 > 0.f) ? v3 : expm1f(v3);
    *(float4*)&out[idx] = make_float4(v0, v1, v2, v3);
}

// ---------------- launcher -----------------------------------------------------
extern "C" void kernel_launch(void* const* d_in, const int* in_sizes, int n_in,
                              void* d_out, int out_size) {
    const float* h = nullptr; const int* adj = nullptr;
    const float* W = nullptr; const float* a = nullptr;
    for (int i = 0; i < n_in; i++) {
        switch (in_sizes[i]) {
            case 1048576:  h   = (const float*)d_in[i]; break;
            case 67108864: adj = (const int*)  d_in[i]; break;
            case 8192:     W   = (const float*)d_in[i]; break;
            case 128:      a   = (const float*)d_in[i]; break;
            default: break;
        }
    }
    float* out = (float*)d_out;

    cudaFuncSetAttribute(k1_proj, cudaFuncAttributeMaxDynamicSharedMemorySize, K1_SMEM);
    cudaFuncSetAttribute(k2_gat, cudaFuncAttributeMaxDynamicSharedMemorySize, SMEM_K2);

    k1_proj<<<NN / K1_ROWS, K1T, K1_SMEM>>>(h, W, a);
    k2_gat<<<64 * JSPLIT, K2T, SMEM_K2>>>(adj);
    k3_final<<<(NN * OUTF) / 1024, 256>>>(out);
    (void)out_size;
}